// round 2
// baseline (speedup 1.0000x reference)
#include <cuda_runtime.h>

#define NUM_NODES 50000
#define C 64
#define NUM_EDGES 800000

// Scratch (allocation-free rule: __device__ globals)
__device__ __align__(16) float g_aggr[NUM_NODES * C];
__device__ float g_deg[NUM_NODES];
__device__ int g_is64;   // 1 if edge_index buffer is int64, 0 if int32

// ---------------------------------------------------------------------------
// Kernel 0: detect edge_index element width.
// Interpret first 4096 entries as int64. Genuine int64 indices are all in
// [0, NUM_NODES). If the buffer is really int32 pairs, the int64 view is
// lo + hi*2^32 with hi = next index (almost surely nonzero) -> out of range.
// ---------------------------------------------------------------------------
__global__ void detect_kernel(const long long* __restrict__ ei64) {
    __shared__ int bad;
    if (threadIdx.x == 0) bad = 0;
    __syncthreads();
    for (int i = threadIdx.x; i < 4096; i += blockDim.x) {
        long long v = ei64[i];
        if (v < 0 || v >= NUM_NODES) bad = 1;
    }
    __syncthreads();
    if (threadIdx.x == 0) g_is64 = bad ? 0 : 1;
}

// ---------------------------------------------------------------------------
// Kernel 1: zero the scratch accumulators (every call — deterministic)
// ---------------------------------------------------------------------------
__global__ void zero_kernel() {
    int i = blockIdx.x * blockDim.x + threadIdx.x;
    const int n4 = NUM_NODES * C / 4;  // 800000 float4
    if (i < n4) ((float4*)g_aggr)[i] = make_float4(0.f, 0.f, 0.f, 0.f);
    if (i < NUM_NODES) g_deg[i] = 0.f;
}

// ---------------------------------------------------------------------------
// Kernel 2: scatter-add x[row] into g_aggr[col], count degree.
// 16 threads per edge, one float4 each. red.global.add.v4.f32 = no return
// trip, 1 instruction per 16B instead of 4 scalar atomics.
// ---------------------------------------------------------------------------
__global__ void scatter_kernel(const float* __restrict__ x,
                               const void* __restrict__ ei_raw) {
    int idx = blockIdx.x * blockDim.x + threadIdx.x;
    if (idx >= NUM_EDGES * 16) return;
    int e     = idx >> 4;
    int chunk = idx & 15;

    long long r, c;
    if (g_is64) {
        const long long* ei = (const long long*)ei_raw;
        r = __ldg(&ei[e]);
        c = __ldg(&ei[NUM_EDGES + e]);
    } else {
        const int* ei = (const int*)ei_raw;
        r = __ldg(&ei[e]);
        c = __ldg(&ei[NUM_EDGES + e]);
    }
    // Defensive: degrade to wrong-answer instead of illegal access.
    if (r < 0 || r >= NUM_NODES || c < 0 || c >= NUM_NODES) return;

    float4 v = __ldg(((const float4*)(x + r * C)) + chunk);
    float* dst = g_aggr + c * C + (chunk << 2);
    asm volatile("red.global.add.v4.f32 [%0], {%1,%2,%3,%4};"
                 :: "l"(dst), "f"(v.x), "f"(v.y), "f"(v.z), "f"(v.w)
                 : "memory");
    if (chunk == 0) atomicAdd(&g_deg[c], 1.0f);
}

// ---------------------------------------------------------------------------
// Kernel 3: out[n] = concat(x[n], aggr[n]/max(deg,1)) @ W^T + b
// W staged in shared transposed as Wt[k][o] (32 KB).
// 16 nodes per 256-thread block; 16 threads per node, 4 outputs each.
// Features staged in shared with stride 132 (pad) -> conflict-free.
// ---------------------------------------------------------------------------
__global__ void gemm_kernel(const float* __restrict__ x,
                            const float* __restrict__ W,
                            const float* __restrict__ b,
                            float* __restrict__ out) {
    __shared__ float Wt[128 * 64];       // [k][o]  32 KB
    __shared__ float feats[16 * 132];    // 16 nodes x 128 feats, padded

    int t = threadIdx.x;

    // Stage W transposed: W is [o][k] row-major (64 x 128)
    #pragma unroll
    for (int i = t; i < 128 * 64; i += 256) {
        int o = i >> 7;
        int k = i & 127;
        Wt[k * 64 + o] = W[i];
    }

    int base = blockIdx.x * 16;

    // Stage features: c < 64 -> x, c >= 64 -> aggr/deg
    for (int i = t; i < 16 * 128; i += 256) {
        int local = i >> 7;
        int c     = i & 127;
        int n     = base + local;
        float v = 0.f;
        if (n < NUM_NODES) {
            if (c < C) v = x[n * C + c];
            else       v = g_aggr[n * C + (c - C)] / fmaxf(g_deg[n], 1.0f);
        }
        feats[local * 132 + c] = v;
    }
    __syncthreads();

    int local = t >> 4;          // node within block: 0..15
    int og    = (t & 15) << 2;   // output group base: 0..60 step 4
    int n     = base + local;
    if (n >= NUM_NODES) return;

    float acc[4];
    #pragma unroll
    for (int j = 0; j < 4; j++) acc[j] = b[og + j];

    const float* f_row = &feats[local * 132];
    #pragma unroll 8
    for (int k = 0; k < 128; k++) {
        float f = f_row[k];
        #pragma unroll
        for (int j = 0; j < 4; j++) acc[j] += f * Wt[k * 64 + og + j];
    }

    #pragma unroll
    for (int j = 0; j < 4; j++) out[n * C + og + j] = acc[j];
}

// ---------------------------------------------------------------------------
extern "C" void kernel_launch(void* const* d_in, const int* in_sizes, int n_in,
                              void* d_out, int out_size) {
    const float* x   = (const float*)d_in[0];
    const void*  ei  = d_in[1];
    const float* W   = (const float*)d_in[2];
    const float* b   = (const float*)d_in[3];
    float*       out = (float*)d_out;

    detect_kernel<<<1, 256>>>((const long long*)ei);
    zero_kernel<<<(NUM_NODES * C / 4 + 255) / 256, 256>>>();
    scatter_kernel<<<(NUM_EDGES * 16) / 256, 256>>>(x, ei);
    gemm_kernel<<<(NUM_NODES + 15) / 16, 256>>>(x, W, b, out);
}

// round 3
// speedup vs baseline: 1.8390x; 1.8390x over previous
#include <cuda_runtime.h>

#define NUM_NODES 50000
#define C 64
#define NUM_EDGES 800000

// Scratch (allocation-free rule: __device__ globals)
__device__ __align__(16) float g_aggr[NUM_NODES * C];
__device__ float g_deg[NUM_NODES];
__device__ int g_is64;   // 1 if edge_index buffer is int64, 0 if int32

// ---------------------------------------------------------------------------
// Kernel 0: detect edge_index element width (int64 vs int32-canonicalized).
// ---------------------------------------------------------------------------
__global__ void detect_kernel(const long long* __restrict__ ei64) {
    __shared__ int bad;
    if (threadIdx.x == 0) bad = 0;
    __syncthreads();
    for (int i = threadIdx.x; i < 4096; i += blockDim.x) {
        long long v = ei64[i];
        if (v < 0 || v >= NUM_NODES) bad = 1;
    }
    __syncthreads();
    if (threadIdx.x == 0) g_is64 = bad ? 0 : 1;
}

// ---------------------------------------------------------------------------
// Kernel 1: zero scratch accumulators (every call — deterministic)
// ---------------------------------------------------------------------------
__global__ void zero_kernel() {
    int i = blockIdx.x * blockDim.x + threadIdx.x;
    const int n4 = NUM_NODES * C / 4;  // 800000 float4
    if (i < n4) ((float4*)g_aggr)[i] = make_float4(0.f, 0.f, 0.f, 0.f);
    if (i < NUM_NODES) g_deg[i] = 0.f;
}

// ---------------------------------------------------------------------------
// Kernel 2: scatter-add x[row] into g_aggr[col], count degree.
// 16 threads/edge, red.global.add.v4.f32 (no return trip).
// ---------------------------------------------------------------------------
__global__ void scatter_kernel(const float* __restrict__ x,
                               const void* __restrict__ ei_raw) {
    int idx = blockIdx.x * blockDim.x + threadIdx.x;
    if (idx >= NUM_EDGES * 16) return;
    int e     = idx >> 4;
    int chunk = idx & 15;

    long long r, c;
    if (g_is64) {
        const long long* ei = (const long long*)ei_raw;
        r = __ldg(&ei[e]);
        c = __ldg(&ei[NUM_EDGES + e]);
    } else {
        const int* ei = (const int*)ei_raw;
        r = __ldg(&ei[e]);
        c = __ldg(&ei[NUM_EDGES + e]);
    }
    if (r < 0 || r >= NUM_NODES || c < 0 || c >= NUM_NODES) return;

    float4 v = __ldg(((const float4*)(x + r * C)) + chunk);
    float* dst = g_aggr + c * C + (chunk << 2);
    asm volatile("red.global.add.v4.f32 [%0], {%1,%2,%3,%4};"
                 :: "l"(dst), "f"(v.x), "f"(v.y), "f"(v.z), "f"(v.w)
                 : "memory");
    if (chunk == 0) atomicAdd(&g_deg[c], 1.0f);
}

// ---------------------------------------------------------------------------
// Kernel 3: out[n] = concat(x[n], aggr[n]*rdeg) @ W^T + b
// Register-tiled: 64 nodes x 64 outs per 256-thread block.
// Thread = 1 node x 16 outputs (8 f32x2 accumulators, fma.rn.f32x2).
// F[k][n] stride 65 (conflict-free scalar LDS); Wt[k][o] stride 68
// (16B-aligned rows; warp-uniform broadcast LDS.128).
// ---------------------------------------------------------------------------
#define WT_STRIDE 68
#define F_STRIDE  65
#define SMEM_WT   0
#define SMEM_F    (128 * WT_STRIDE)                 // floats
#define SMEM_RD   (SMEM_F + 128 * F_STRIDE)         // floats
#define GEMM_SMEM ((SMEM_RD + 64) * 4)              // bytes = 68352

__global__ void __launch_bounds__(256, 3)
gemm_kernel(const float* __restrict__ x,
            const float* __restrict__ W,
            const float* __restrict__ b,
            float* __restrict__ out) {
    extern __shared__ float sm[];
    float* Wt   = sm + SMEM_WT;   // [k][o] stride 68
    float* F    = sm + SMEM_F;    // [k][n] stride 65
    float* rdeg = sm + SMEM_RD;   // [64]

    int t = threadIdx.x;
    int base = blockIdx.x * 64;

    // Stage W transposed: W is [o][k] row-major (64 x 128)
    #pragma unroll
    for (int i = t; i < 64 * 128; i += 256) {
        int o = i >> 7;
        int k = i & 127;
        Wt[k * WT_STRIDE + o] = W[i];
    }

    // Per-node reciprocal degree
    if (t < 64) {
        int n = base + t;
        rdeg[t] = (n < NUM_NODES) ? __frcp_rn(fmaxf(g_deg[n], 1.0f)) : 0.0f;
    }
    __syncthreads();

    // Stage features transposed: F[c][n]; coalesced gmem reads.
    #pragma unroll
    for (int i = t; i < 64 * 128; i += 256) {
        int nl = i >> 7;
        int c  = i & 127;
        int n  = base + nl;
        float v = 0.0f;
        if (n < NUM_NODES) {
            v = (c < C) ? x[n * C + c]
                        : g_aggr[n * C + (c - C)] * rdeg[nl];
        }
        F[c * F_STRIDE + nl] = v;
    }
    __syncthreads();

    int nl = t & 63;          // node within block
    int o0 = (t >> 6) << 4;   // output base: 0,16,32,48 (warp-uniform)
    int n  = base + nl;

    // 8 packed f32x2 accumulators = 16 outputs
    unsigned long long acc[8];
    #pragma unroll
    for (int p = 0; p < 8; p++) acc[p] = 0ULL;

    const float* frow = F + nl;
    const float* wrow = Wt + o0;

    #pragma unroll 4
    for (int k = 0; k < 128; k++) {
        float f = frow[k * F_STRIDE];
        unsigned long long fp;
        asm("mov.b64 %0, {%1, %1};" : "=l"(fp) : "f"(f));
        const ulonglong2* wv = (const ulonglong2*)(wrow + k * WT_STRIDE);
        ulonglong2 w01 = wv[0];   // outs o0..o0+3
        ulonglong2 w23 = wv[1];   // o0+4..7
        ulonglong2 w45 = wv[2];   // o0+8..11
        ulonglong2 w67 = wv[3];   // o0+12..15
        asm("fma.rn.f32x2 %0, %1, %2, %0;" : "+l"(acc[0]) : "l"(w01.x), "l"(fp));
        asm("fma.rn.f32x2 %0, %1, %2, %0;" : "+l"(acc[1]) : "l"(w01.y), "l"(fp));
        asm("fma.rn.f32x2 %0, %1, %2, %0;" : "+l"(acc[2]) : "l"(w23.x), "l"(fp));
        asm("fma.rn.f32x2 %0, %1, %2, %0;" : "+l"(acc[3]) : "l"(w23.y), "l"(fp));
        asm("fma.rn.f32x2 %0, %1, %2, %0;" : "+l"(acc[4]) : "l"(w45.x), "l"(fp));
        asm("fma.rn.f32x2 %0, %1, %2, %0;" : "+l"(acc[5]) : "l"(w45.y), "l"(fp));
        asm("fma.rn.f32x2 %0, %1, %2, %0;" : "+l"(acc[6]) : "l"(w67.x), "l"(fp));
        asm("fma.rn.f32x2 %0, %1, %2, %0;" : "+l"(acc[7]) : "l"(w67.y), "l"(fp));
    }

    if (n >= NUM_NODES) return;

    // Unpack, add bias, store as 4 x STG.128
    float* orow = out + n * 64 + o0;
    #pragma unroll
    for (int j = 0; j < 4; j++) {
        float lo0, hi0, lo1, hi1;
        asm("mov.b64 {%0, %1}, %2;" : "=f"(lo0), "=f"(hi0) : "l"(acc[2 * j]));
        asm("mov.b64 {%0, %1}, %2;" : "=f"(lo1), "=f"(hi1) : "l"(acc[2 * j + 1]));
        float4 r;
        r.x = lo0 + b[o0 + 4 * j + 0];
        r.y = hi0 + b[o0 + 4 * j + 1];
        r.z = lo1 + b[o0 + 4 * j + 2];
        r.w = hi1 + b[o0 + 4 * j + 3];
        *(float4*)(orow + 4 * j) = r;
    }
}

// ---------------------------------------------------------------------------
extern "C" void kernel_launch(void* const* d_in, const int* in_sizes, int n_in,
                              void* d_out, int out_size) {
    const float* x   = (const float*)d_in[0];
    const void*  ei  = d_in[1];
    const float* W   = (const float*)d_in[2];
    const float* b   = (const float*)d_in[3];
    float*       out = (float*)d_out;

    cudaFuncSetAttribute(gemm_kernel,
                         cudaFuncAttributeMaxDynamicSharedMemorySize, GEMM_SMEM);

    detect_kernel<<<1, 256>>>((const long long*)ei);
    zero_kernel<<<(NUM_NODES * C / 4 + 255) / 256, 256>>>();
    scatter_kernel<<<(NUM_EDGES * 16) / 256, 256>>>(x, ei);
    gemm_kernel<<<(NUM_NODES + 63) / 64, 256, GEMM_SMEM>>>(x, W, b, out);
}